// round 1
// baseline (speedup 1.0000x reference)
#include <cuda_runtime.h>

// BilateralSliceApply on GB300.
// grid:  (4, 12, 8, 16, 16) f32   -> cached per-batch in SMEM, z-stride padded
// guide: (4, 1024, 1024) f32
// image: (4, 3, 1024, 1024) f32
// out:   (4, 3, 1024, 1024) f32

#define GD 8
#define GH 16
#define GW 16
#define NC 12
#define W_IMG 1024
#define H_IMG 1024
#define ZSTRIDE 3076                 // 16*16*12 = 3072, +4 floats pad -> bank-conflict-free across z
#define SMEM_BYTES (GD * ZSTRIDE * 4)
#define GRID_PER_B (NC * GD * GH * GW)   // 24576

__device__ __forceinline__ unsigned long long pack2(float v) {
    unsigned long long r;
    asm("mov.b64 %0, {%1, %1};" : "=l"(r) : "f"(v));
    return r;
}
__device__ __forceinline__ void fma2(unsigned long long &acc, unsigned long long a,
                                     unsigned long long w) {
    asm("fma.rn.f32x2 %0, %1, %2, %0;" : "+l"(acc) : "l"(a), "l"(w));
}
__device__ __forceinline__ void unpack2(unsigned long long v, float &lo, float &hi) {
    asm("mov.b64 {%0, %1}, %2;" : "=f"(lo), "=f"(hi) : "l"(v));
}

__global__ void __launch_bounds__(256, 2) bsa_kernel(
    const float* __restrict__ grid,
    const float* __restrict__ guide,
    const float* __restrict__ image,
    float* __restrict__ out)
{
    extern __shared__ float sg[];
    const int b = blockIdx.y;

    // ---- Stage grid slab for this batch into SMEM, layout [z][y*16+x][c], z padded ----
    const float* gb = grid + b * GRID_PER_B;
    #pragma unroll 4
    for (int i = threadIdx.x; i < GRID_PER_B; i += 256) {
        int c   = i >> 11;        // / (8*16*16)
        int rem = i & 2047;
        int z   = rem >> 8;       // / 256
        int yx  = rem & 255;
        sg[z * ZSTRIDE + yx * NC + c] = gb[i];
    }
    __syncthreads();

    const float* gu = guide + b * (H_IMG * W_IMG);
    const float* im = image + b * 3 * (H_IMG * W_IMG);
    float*       ob = out   + b * 3 * (H_IMG * W_IMG);

    const int n_groups = H_IMG * (W_IMG / 4);   // 262144 float4 pixel groups
    const int stride   = gridDim.x * blockDim.x;

    for (int idx = blockIdx.x * blockDim.x + threadIdx.x; idx < n_groups; idx += stride) {
        const int y   = idx >> 8;        // / 256
        const int x4  = idx & 255;
        const int px0 = x4 << 2;

        const float4 g4 = reinterpret_cast<const float4*>(gu + y * W_IMG)[x4];
        const float4 r4 = reinterpret_cast<const float4*>(im + 0 * 1048576 + y * W_IMG)[x4];
        const float4 q4 = reinterpret_cast<const float4*>(im + 1 * 1048576 + y * W_IMG)[x4];
        const float4 b4 = reinterpret_cast<const float4*>(im + 2 * 1048576 + y * W_IMG)[x4];

        const float gv[4]  = {g4.x, g4.y, g4.z, g4.w};
        const float rv[4]  = {r4.x, r4.y, r4.z, r4.w};
        const float qv[4]  = {q4.x, q4.y, q4.z, q4.w};
        const float bv[4]  = {b4.x, b4.y, b4.z, b4.w};

        // y interpolation state (shared by the 4 pixels of this group)
        const float gy  = ((float)y + 0.5f) * (16.0f / 1024.0f);
        const float fym = floorf(gy - 0.5f);
        const float ty  = gy - 0.5f - fym;
        const int   ify = (int)fym;
        const int   iy0 = min(max(ify, 0), GH - 1);
        const int   iy1 = min(max(ify + 1, 0), GH - 1);
        const float wy0 = 1.0f - ty, wy1 = ty;
        const int   ro0 = iy0 * (GW * NC);
        const int   ro1 = iy1 * (GW * NC);

        float oR[4], oG[4], oB[4];

        #pragma unroll
        for (int j = 0; j < 4; ++j) {
            const float gx  = ((float)(px0 + j) + 0.5f) * (16.0f / 1024.0f);
            const float fxm = floorf(gx - 0.5f);
            const float tx  = gx - 0.5f - fxm;
            const int   ifx = (int)fxm;
            const int   ix0 = min(max(ifx, 0), GW - 1);
            const int   ix1 = min(max(ifx + 1, 0), GW - 1);
            const float wx0 = 1.0f - tx, wx1 = tx;

            const float gz  = gv[j] * 8.0f;
            const float fzm = floorf(gz - 0.5f);
            const float tz  = gz - 0.5f - fzm;
            const int   ifz = (int)fzm;
            const int   iz0 = min(max(ifz, 0), GD - 1);
            const int   iz1 = min(max(ifz + 1, 0), GD - 1);
            const float wz0 = 1.0f - tz, wz1 = tz;

            const int zo0 = iz0 * ZSTRIDE, zo1 = iz1 * ZSTRIDE;
            const int co0 = ix0 * NC,      co1 = ix1 * NC;

            const float wa = wz0 * wy0, wb = wz0 * wy1;
            const float wc = wz1 * wy0, wd = wz1 * wy1;

            unsigned long long a0 = 0, a1 = 0, a2 = 0, a3 = 0, a4 = 0, a5 = 0;

            #define TAP(off, w) do {                                                   \
                const ulonglong2* _p = reinterpret_cast<const ulonglong2*>(sg + (off));\
                const unsigned long long _w2 = pack2(w);                               \
                ulonglong2 _q0 = _p[0];                                                \
                ulonglong2 _q1 = _p[1];                                                \
                ulonglong2 _q2 = _p[2];                                                \
                fma2(a0, _q0.x, _w2); fma2(a1, _q0.y, _w2);                            \
                fma2(a2, _q1.x, _w2); fma2(a3, _q1.y, _w2);                            \
                fma2(a4, _q2.x, _w2); fma2(a5, _q2.y, _w2);                            \
            } while (0)

            TAP(zo0 + ro0 + co0, wa * wx0);
            TAP(zo0 + ro0 + co1, wa * wx1);
            TAP(zo0 + ro1 + co0, wb * wx0);
            TAP(zo0 + ro1 + co1, wb * wx1);
            TAP(zo1 + ro0 + co0, wc * wx0);
            TAP(zo1 + ro0 + co1, wc * wx1);
            TAP(zo1 + ro1 + co0, wd * wx0);
            TAP(zo1 + ro1 + co1, wd * wx1);
            #undef TAP

            float c0, c1, c2, c3, c4, c5, c6, c7, c8, c9, c10, c11;
            unpack2(a0, c0, c1);
            unpack2(a1, c2, c3);
            unpack2(a2, c4, c5);
            unpack2(a3, c6, c7);
            unpack2(a4, c8, c9);
            unpack2(a5, c10, c11);

            const float R = rv[j], G = qv[j], Bc = bv[j];
            oR[j] = fmaf(c0, R, fmaf(c1, G, fmaf(c2,  Bc, c3)));
            oG[j] = fmaf(c4, R, fmaf(c5, G, fmaf(c6,  Bc, c7)));
            oB[j] = fmaf(c8, R, fmaf(c9, G, fmaf(c10, Bc, c11)));
        }

        reinterpret_cast<float4*>(ob + 0 * 1048576 + y * W_IMG)[x4] =
            make_float4(oR[0], oR[1], oR[2], oR[3]);
        reinterpret_cast<float4*>(ob + 1 * 1048576 + y * W_IMG)[x4] =
            make_float4(oG[0], oG[1], oG[2], oG[3]);
        reinterpret_cast<float4*>(ob + 2 * 1048576 + y * W_IMG)[x4] =
            make_float4(oB[0], oB[1], oB[2], oB[3]);
    }
}

extern "C" void kernel_launch(void* const* d_in, const int* in_sizes, int n_in,
                              void* d_out, int out_size)
{
    // Identify inputs robustly by element count.
    const float* grid  = nullptr;
    const float* guide = nullptr;
    const float* image = nullptr;
    for (int i = 0; i < n_in; ++i) {
        if (in_sizes[i] == 4 * GRID_PER_B)            grid  = (const float*)d_in[i];
        else if (in_sizes[i] == 4 * H_IMG * W_IMG)     guide = (const float*)d_in[i];
        else if (in_sizes[i] == 4 * 3 * H_IMG * W_IMG) image = (const float*)d_in[i];
    }
    float* out = (float*)d_out;

    cudaFuncSetAttribute(bsa_kernel, cudaFuncAttributeMaxDynamicSharedMemorySize, SMEM_BYTES);

    dim3 gr(74, 4);   // 296 blocks = 2 per SM x 148 SMs
    bsa_kernel<<<gr, 256, SMEM_BYTES>>>(grid, guide, image, out);
}

// round 2
// speedup vs baseline: 1.9455x; 1.9455x over previous
#include <cuda_runtime.h>

// BilateralSliceApply on GB300 — row-wise y-prefold version.
// grid:  (4, 12, 8, 16, 16) f32
// guide: (4, 1024, 1024) f32
// image: (4, 3, 1024, 1024) f32
// out:   (4, 3, 1024, 1024) f32
//
// Per image row, pre-interpolate the grid in y:
//   G_y[z][x][c] = wy0*G[z][iy0][x][c] + wy1*G[z][iy1][x][c]
// (1536 floats, 6 KB), then each pixel does only 4 taps (2z x 2x) = 192 B LDS.

#define GD 8
#define GH 16
#define GW 16
#define NC 12
#define W_IMG 1024
#define H_IMG 1024
#define GRID_PER_B (NC * GD * GH * GW)   // 24576
#define ZS 196                            // z-stride in G_y (16*12=192, +4 pad -> banks 4z mod 32 distinct)
#define GY_SZ (GD * ZS)                   // 1568 floats per buffer
#define ROWS_PER_BLOCK 4

__device__ __forceinline__ unsigned long long pack2(float v) {
    unsigned long long r;
    asm("mov.b64 %0, {%1, %1};" : "=l"(r) : "f"(v));
    return r;
}
__device__ __forceinline__ void fma2(unsigned long long &acc, unsigned long long a,
                                     unsigned long long w) {
    asm("fma.rn.f32x2 %0, %1, %2, %0;" : "+l"(acc) : "l"(a), "l"(w));
}
__device__ __forceinline__ void unpack2(unsigned long long v, float &lo, float &hi) {
    asm("mov.b64 {%0, %1}, %2;" : "=f"(lo), "=f"(hi) : "l"(v));
}

__global__ void __launch_bounds__(256, 3) bsa_kernel(
    const float* __restrict__ grid,
    const float* __restrict__ guide,
    const float* __restrict__ image,
    float* __restrict__ out)
{
    __shared__ __align__(16) float gybuf[2][GY_SZ];

    const int b   = blockIdx.y;
    const int tid = threadIdx.x;

    const float* gb = grid  + b * GRID_PER_B;
    const float* gu = guide + b * (H_IMG * W_IMG);
    const float* im = image + b * 3 * (H_IMG * W_IMG);
    float*       ob = out   + b * 3 * (H_IMG * W_IMG);

    const int row0 = blockIdx.x * ROWS_PER_BLOCK;

    for (int k = 0; k < ROWS_PER_BLOCK; ++k) {
        const int y = row0 + k;

        // ---- per-row y interpolation state ----
        const float gyv = ((float)y + 0.5f) * (16.0f / 1024.0f);
        const float fym = floorf(gyv - 0.5f);
        const float ty  = gyv - 0.5f - fym;
        const int   ify = (int)fym;
        const int   iy0 = min(max(ify, 0), GH - 1);
        const int   iy1 = min(max(ify + 1, 0), GH - 1);
        const float wy0 = 1.0f - ty, wy1 = ty;

        float* buf = gybuf[k & 1];

        // ---- stage y-prefolded grid row: 1536 values, 6 per thread ----
        #pragma unroll
        for (int t = 0; t < 6; ++t) {
            const int i   = tid + t * 256;          // [0,1536)
            const int z   = i / 192;
            const int rem = i - z * 192;
            const int x   = rem / 12;
            const int c   = rem - x * 12;
            const float* gp = gb + c * (GD * GH * GW) + z * (GH * GW) + x;
            buf[z * ZS + x * NC + c] = wy0 * gp[iy0 * GW] + wy1 * gp[iy1 * GW];
        }
        __syncthreads();   // also separates row k's reads from row k+2's writes (double buffer)

        // ---- process this row: thread tid owns float4 group x4 = tid ----
        const int x4  = tid;
        const int px0 = x4 << 2;

        const float4 g4 = reinterpret_cast<const float4*>(gu + y * W_IMG)[x4];
        const float4 r4 = reinterpret_cast<const float4*>(im + 0 * 1048576 + y * W_IMG)[x4];
        const float4 q4 = reinterpret_cast<const float4*>(im + 1 * 1048576 + y * W_IMG)[x4];
        const float4 b4 = reinterpret_cast<const float4*>(im + 2 * 1048576 + y * W_IMG)[x4];

        const float gv[4] = {g4.x, g4.y, g4.z, g4.w};
        const float rv[4] = {r4.x, r4.y, r4.z, r4.w};
        const float qv[4] = {q4.x, q4.y, q4.z, q4.w};
        const float bv[4] = {b4.x, b4.y, b4.z, b4.w};

        float oR[4], oG[4], oB[4];

        #pragma unroll
        for (int j = 0; j < 4; ++j) {
            // x interpolation
            const float gx  = ((float)(px0 + j) + 0.5f) * (16.0f / 1024.0f);
            const float fxm = floorf(gx - 0.5f);
            const float tx  = gx - 0.5f - fxm;
            const int   ifx = (int)fxm;
            const int   ix0 = min(max(ifx, 0), GW - 1);
            const int   ix1 = min(max(ifx + 1, 0), GW - 1);
            const float wx0 = 1.0f - tx, wx1 = tx;

            // z interpolation (guide-driven)
            const float gz  = gv[j] * 8.0f;
            const float fzm = floorf(gz - 0.5f);
            const float tz  = gz - 0.5f - fzm;
            const int   ifz = (int)fzm;
            const int   iz0 = min(max(ifz, 0), GD - 1);
            const int   iz1 = min(max(ifz + 1, 0), GD - 1);
            const float wz0 = 1.0f - tz, wz1 = tz;

            const int zo0 = iz0 * ZS, zo1 = iz1 * ZS;
            const int co0 = ix0 * NC, co1 = ix1 * NC;

            unsigned long long a0 = 0, a1 = 0, a2 = 0, a3 = 0, a4 = 0, a5 = 0;

            #define TAP(off, w) do {                                                    \
                const ulonglong2* _p = reinterpret_cast<const ulonglong2*>(buf + (off));\
                const unsigned long long _w2 = pack2(w);                                \
                ulonglong2 _q0 = _p[0];                                                 \
                ulonglong2 _q1 = _p[1];                                                 \
                ulonglong2 _q2 = _p[2];                                                 \
                fma2(a0, _q0.x, _w2); fma2(a1, _q0.y, _w2);                             \
                fma2(a2, _q1.x, _w2); fma2(a3, _q1.y, _w2);                             \
                fma2(a4, _q2.x, _w2); fma2(a5, _q2.y, _w2);                             \
            } while (0)

            TAP(zo0 + co0, wz0 * wx0);
            TAP(zo0 + co1, wz0 * wx1);
            TAP(zo1 + co0, wz1 * wx0);
            TAP(zo1 + co1, wz1 * wx1);
            #undef TAP

            float c0, c1, c2, c3, c4, c5, c6, c7, c8, c9, c10, c11;
            unpack2(a0, c0, c1);
            unpack2(a1, c2, c3);
            unpack2(a2, c4, c5);
            unpack2(a3, c6, c7);
            unpack2(a4, c8, c9);
            unpack2(a5, c10, c11);

            const float R = rv[j], G = qv[j], Bc = bv[j];
            oR[j] = fmaf(c0, R, fmaf(c1, G, fmaf(c2,  Bc, c3)));
            oG[j] = fmaf(c4, R, fmaf(c5, G, fmaf(c6,  Bc, c7)));
            oB[j] = fmaf(c8, R, fmaf(c9, G, fmaf(c10, Bc, c11)));
        }

        reinterpret_cast<float4*>(ob + 0 * 1048576 + y * W_IMG)[x4] =
            make_float4(oR[0], oR[1], oR[2], oR[3]);
        reinterpret_cast<float4*>(ob + 1 * 1048576 + y * W_IMG)[x4] =
            make_float4(oG[0], oG[1], oG[2], oG[3]);
        reinterpret_cast<float4*>(ob + 2 * 1048576 + y * W_IMG)[x4] =
            make_float4(oB[0], oB[1], oB[2], oB[3]);
    }
}

extern "C" void kernel_launch(void* const* d_in, const int* in_sizes, int n_in,
                              void* d_out, int out_size)
{
    const float* grid  = nullptr;
    const float* guide = nullptr;
    const float* image = nullptr;
    for (int i = 0; i < n_in; ++i) {
        if (in_sizes[i] == 4 * GRID_PER_B)             grid  = (const float*)d_in[i];
        else if (in_sizes[i] == 4 * H_IMG * W_IMG)     guide = (const float*)d_in[i];
        else if (in_sizes[i] == 4 * 3 * H_IMG * W_IMG) image = (const float*)d_in[i];
    }
    float* out = (float*)d_out;

    dim3 gr(H_IMG / ROWS_PER_BLOCK / 1, 4);   // 256 x 4 blocks, 4 rows each
    gr.x = H_IMG / ROWS_PER_BLOCK;            // 256
    bsa_kernel<<<gr, 256>>>(grid, guide, image, out);
}

// round 3
// speedup vs baseline: 2.1116x; 1.0853x over previous
#include <cuda_runtime.h>

// BilateralSliceApply on GB300 — y-prefold + conflict-free (z,x) SMEM layout.
// grid:  (4, 12, 8, 16, 16) f32
// guide: (4, 1024, 1024) f32
// image: (4, 3, 1024, 1024) f32
// out:   (4, 3, 1024, 1024) f32
//
// Per row: G_y[z][x][c] = wy0*G[z][iy0][x][c] + wy1*G[z][iy1][x][c]
// SMEM layout: cell (z,x) padded to 64 B (16 floats, 12 used), z-stride 1040 B.
//   addr mod 128 = (16*z + 64*x + 16*c4) mod 128 -> distinct 16B group per z
//   when x,c4 uniform across a phase => conflict-free taps.

#define GD 8
#define GH 16
#define GW 16
#define NC 12
#define W_IMG 1024
#define H_IMG 1024
#define GRID_PER_B (NC * GD * GH * GW)   // 24576
#define XS 16                             // x-stride in floats (64 B cell)
#define ZS 260                            // z-stride in floats (1040 B; 1040 mod 128 = 16)
#define GY_SZ (GD * ZS)                   // 2080 floats per buffer
#define ROWS_PER_BLOCK 4

__device__ __forceinline__ unsigned long long pack2(float v) {
    unsigned long long r;
    asm("mov.b64 %0, {%1, %1};" : "=l"(r) : "f"(v));
    return r;
}
__device__ __forceinline__ void fma2(unsigned long long &acc, unsigned long long a,
                                     unsigned long long w) {
    asm("fma.rn.f32x2 %0, %1, %2, %0;" : "+l"(acc) : "l"(a), "l"(w));
}
__device__ __forceinline__ void unpack2(unsigned long long v, float &lo, float &hi) {
    asm("mov.b64 {%0, %1}, %2;" : "=f"(lo), "=f"(hi) : "l"(v));
}

__global__ void __launch_bounds__(256, 3) bsa_kernel(
    const float* __restrict__ grid,
    const float* __restrict__ guide,
    const float* __restrict__ image,
    float* __restrict__ out)
{
    __shared__ __align__(16) float gybuf[2][GY_SZ];

    const int b   = blockIdx.y;
    const int tid = threadIdx.x;

    const float* gb = grid  + b * GRID_PER_B;
    const float* gu = guide + b * (H_IMG * W_IMG);
    const float* im = image + b * 3 * (H_IMG * W_IMG);
    float*       ob = out   + b * 3 * (H_IMG * W_IMG);

    const int row0 = blockIdx.x * ROWS_PER_BLOCK;

    for (int k = 0; k < ROWS_PER_BLOCK; ++k) {
        const int y = row0 + k;

        // ---- per-row y interpolation state ----
        const float gyv = ((float)y + 0.5f) * (16.0f / 1024.0f);
        const float fym = floorf(gyv - 0.5f);
        const float ty  = gyv - 0.5f - fym;
        const int   ify = (int)fym;
        const int   iy0 = min(max(ify, 0), GH - 1);
        const int   iy1 = min(max(ify + 1, 0), GH - 1);
        const float wy0 = 1.0f - ty, wy1 = ty;

        float* buf = gybuf[k & 1];

        // ---- stage y-prefolded grid row: 1536 values, 6 per thread ----
        // i = ((c*8)+z)*16 + x  -> consecutive threads read consecutive x (coalesced)
        #pragma unroll
        for (int t = 0; t < 6; ++t) {
            const int i = tid + t * 256;            // [0, 1536)
            const int c = i >> 7;                   // /128
            const int z = (i >> 4) & 7;
            const int x = i & 15;
            const float* gp = gb + c * (GD * GH * GW) + z * (GH * GW) + x;
            buf[z * ZS + x * XS + c] = wy0 * gp[iy0 * GW] + wy1 * gp[iy1 * GW];
        }
        __syncthreads();   // double buffer separates row k reads from row k+2 writes

        // ---- process this row: thread tid owns float4 group x4 = tid ----
        const int x4  = tid;
        const int px0 = x4 << 2;

        const float4 g4 = reinterpret_cast<const float4*>(gu + y * W_IMG)[x4];
        const float4 r4 = reinterpret_cast<const float4*>(im + 0 * 1048576 + y * W_IMG)[x4];
        const float4 q4 = reinterpret_cast<const float4*>(im + 1 * 1048576 + y * W_IMG)[x4];
        const float4 b4 = reinterpret_cast<const float4*>(im + 2 * 1048576 + y * W_IMG)[x4];

        const float gv[4] = {g4.x, g4.y, g4.z, g4.w};
        const float rv[4] = {r4.x, r4.y, r4.z, r4.w};
        const float qv[4] = {q4.x, q4.y, q4.z, q4.w};
        const float bv[4] = {b4.x, b4.y, b4.z, b4.w};

        float oR[4], oG[4], oB[4];

        #pragma unroll
        for (int j = 0; j < 4; ++j) {
            // x interpolation
            const float gx  = ((float)(px0 + j) + 0.5f) * (16.0f / 1024.0f);
            const float fxm = floorf(gx - 0.5f);
            const float tx  = gx - 0.5f - fxm;
            const int   ifx = (int)fxm;
            const int   ix0 = min(max(ifx, 0), GW - 1);
            const int   ix1 = min(max(ifx + 1, 0), GW - 1);
            const float wx0 = 1.0f - tx, wx1 = tx;

            // z interpolation (guide-driven)
            const float gz  = gv[j] * 8.0f;
            const float fzm = floorf(gz - 0.5f);
            const float tz  = gz - 0.5f - fzm;
            const int   ifz = (int)fzm;
            const int   iz0 = min(max(ifz, 0), GD - 1);
            const int   iz1 = min(max(ifz + 1, 0), GD - 1);
            const float wz0 = 1.0f - tz, wz1 = tz;

            const int zo0 = iz0 * ZS, zo1 = iz1 * ZS;
            const int co0 = ix0 * XS, co1 = ix1 * XS;

            unsigned long long a0 = 0, a1 = 0, a2 = 0, a3 = 0, a4 = 0, a5 = 0;

            #define TAP(off, w) do {                                                    \
                const ulonglong2* _p = reinterpret_cast<const ulonglong2*>(buf + (off));\
                const unsigned long long _w2 = pack2(w);                                \
                ulonglong2 _q0 = _p[0];                                                 \
                ulonglong2 _q1 = _p[1];                                                 \
                ulonglong2 _q2 = _p[2];                                                 \
                fma2(a0, _q0.x, _w2); fma2(a1, _q0.y, _w2);                             \
                fma2(a2, _q1.x, _w2); fma2(a3, _q1.y, _w2);                             \
                fma2(a4, _q2.x, _w2); fma2(a5, _q2.y, _w2);                             \
            } while (0)

            TAP(zo0 + co0, wz0 * wx0);
            TAP(zo0 + co1, wz0 * wx1);
            TAP(zo1 + co0, wz1 * wx0);
            TAP(zo1 + co1, wz1 * wx1);
            #undef TAP

            float c0, c1, c2, c3, c4, c5, c6, c7, c8, c9, c10, c11;
            unpack2(a0, c0, c1);
            unpack2(a1, c2, c3);
            unpack2(a2, c4, c5);
            unpack2(a3, c6, c7);
            unpack2(a4, c8, c9);
            unpack2(a5, c10, c11);

            const float R = rv[j], G = qv[j], Bc = bv[j];
            oR[j] = fmaf(c0, R, fmaf(c1, G, fmaf(c2,  Bc, c3)));
            oG[j] = fmaf(c4, R, fmaf(c5, G, fmaf(c6,  Bc, c7)));
            oB[j] = fmaf(c8, R, fmaf(c9, G, fmaf(c10, Bc, c11)));
        }

        reinterpret_cast<float4*>(ob + 0 * 1048576 + y * W_IMG)[x4] =
            make_float4(oR[0], oR[1], oR[2], oR[3]);
        reinterpret_cast<float4*>(ob + 1 * 1048576 + y * W_IMG)[x4] =
            make_float4(oG[0], oG[1], oG[2], oG[3]);
        reinterpret_cast<float4*>(ob + 2 * 1048576 + y * W_IMG)[x4] =
            make_float4(oB[0], oB[1], oB[2], oB[3]);
    }
}

extern "C" void kernel_launch(void* const* d_in, const int* in_sizes, int n_in,
                              void* d_out, int out_size)
{
    const float* grid  = nullptr;
    const float* guide = nullptr;
    const float* image = nullptr;
    for (int i = 0; i < n_in; ++i) {
        if (in_sizes[i] == 4 * GRID_PER_B)             grid  = (const float*)d_in[i];
        else if (in_sizes[i] == 4 * H_IMG * W_IMG)     guide = (const float*)d_in[i];
        else if (in_sizes[i] == 4 * 3 * H_IMG * W_IMG) image = (const float*)d_in[i];
    }
    float* out = (float*)d_out;

    dim3 gr(H_IMG / ROWS_PER_BLOCK, 4);   // 256 x 4 = 1024 blocks, 4 rows each
    bsa_kernel<<<gr, 256>>>(grid, guide, image, out);
}